// round 3
// baseline (speedup 1.0000x reference)
#include <cuda_runtime.h>
#include <cuda_bf16.h>

// Problem constants (match reference)
#define B_  32
#define S_  128
#define I_  64
#define H_  1024
#define T_  4          // NUM_TIME_STEPS
#define DECAY      0.9f
#define THRESHOLD  1.0f
#define BETA       5.0f

#define TPB 128        // threads per block (h-tile)

// Fused kernel: one thread owns one (b, h) lane.
//  - encoding column enc[0..63][h] cached in 64 registers (reused across all 128 s-steps)
//  - per s: drive = sum_i enc[i]*x[b,s,i,h], loads front-batched in two groups of 32
//    to keep ~32 loads in flight per thread (bandwidth-delay coverage)
//  - then 4 LIF steps (decay, surrogate sigmoid spike, subtractive reset), 4 coalesced stores
__global__ __launch_bounds__(TPB, 1)
void lif_fused_kernel(const float* __restrict__ x,
                      const float* __restrict__ enc,
                      float* __restrict__ out)
{
    const int h = blockIdx.x * TPB + threadIdx.x;   // 0..1023
    const int b = blockIdx.y;                        // 0..31

    // Cache encoding column in registers (64 regs, reused 128x)
    float e[I_];
#pragma unroll
    for (int i = 0; i < I_; i++)
        e[i] = __ldg(enc + i * H_ + h);

    const float* xb = x + (size_t)b * S_ * I_ * H_ + h;
    float*       ob = out + (size_t)b * S_ * T_ * H_ + h;

    float v = 0.0f;

    for (int s = 0; s < S_; s++) {
        const float* xs = xb + (size_t)s * (I_ * H_);

        // --- drive = sum_i e[i] * x[b,s,i,h], 4-way accumulator tree ---
        float d0 = 0.f, d1 = 0.f, d2 = 0.f, d3 = 0.f;
#pragma unroll
        for (int half = 0; half < 2; half++) {
            float xv[32];                // front-batch 32 loads -> MLP ~32
#pragma unroll
            for (int i = 0; i < 32; i++)
                xv[i] = __ldg(xs + (half * 32 + i) * H_);
#pragma unroll
            for (int i = 0; i < 32; i++) {
                const float ev = e[half * 32 + i];
                switch (i & 3) {
                    case 0: d0 = fmaf(ev, xv[i], d0); break;
                    case 1: d1 = fmaf(ev, xv[i], d1); break;
                    case 2: d2 = fmaf(ev, xv[i], d2); break;
                    default: d3 = fmaf(ev, xv[i], d3); break;
                }
            }
        }
        const float drive = (d0 + d1) + (d2 + d3);

        // --- 4 LIF steps with the same drive ---
        float* os = ob + (size_t)s * T_ * H_;
#pragma unroll
        for (int t = 0; t < T_; t++) {
            v = DECAY * v + drive;
            // sigmoid(BETA*(v - THRESHOLD)) = 1 / (1 + exp(BETA*(THRESHOLD - v)))
            const float ex = __expf(BETA * (THRESHOLD - v));
            const float spike = __fdividef(1.0f, 1.0f + ex);
            v -= spike * THRESHOLD;
            os[t * H_] = spike;
        }
    }

    // v_final appended after the output sequence
    out[(size_t)B_ * S_ * T_ * H_ + (size_t)b * H_ + h] = v;
}

extern "C" void kernel_launch(void* const* d_in, const int* in_sizes, int n_in,
                              void* d_out, int out_size)
{
    const float* x   = (const float*)d_in[0];   // [32,128,64,1024] f32
    const float* enc = (const float*)d_in[1];   // [64,1024] f32
    float* out = (float*)d_out;                 // [32*512*1024 + 32*1024] f32

    dim3 grid(H_ / TPB, B_);   // (8, 32) = 256 blocks, all co-resident
    lif_fused_kernel<<<grid, TPB>>>(x, enc, out);
}